// round 12
// baseline (speedup 1.0000x reference)
#include <cuda_runtime.h>
#include <cstdint>

#define EPS_P 0.001f

// ---------------- scratch (device globals: no allocation, graph-safe) ----------------
__device__ float g_WinT[1024 * 1536];   // in_proj_weight^T  (K=1024 x N=1536)
__device__ float g_WoutT[1024 * 1024];  // out_proj_weight^T (1024 x 1024)
__device__ float g_Q[2048 * 1024];      // projected queries
__device__ float g_K[2048 * 256];       // projected keys
__device__ float g_V[2048 * 256];       // projected values
__device__ float g_KT[256 * 2048];      // keys transposed (embed x token)
__device__ float g_P[32 * 1024 * 1024]; // sigmoid probs -> phi (in place)
__device__ float g_XO[2048 * 1024];     // attention output (token-major, per-head cols)

// ---------------- f32x2 packed-FMA helpers (FFMA2 only reachable via PTX) ----------------
__device__ __forceinline__ unsigned long long fma_f32x2(unsigned long long a,
                                                        unsigned long long b,
                                                        unsigned long long c) {
    unsigned long long d;
    asm("fma.rn.f32x2 %0, %1, %2, %3;" : "=l"(d) : "l"(a), "l"(b), "l"(c));
    return d;
}
__device__ __forceinline__ unsigned long long dup_f32(float x) {
    unsigned long long d;
    asm("mov.b64 %0, {%1, %1};" : "=l"(d) : "f"(x));
    return d;
}
__device__ __forceinline__ float2 unpack_f32x2(unsigned long long v) {
    float2 r;
    asm("mov.b64 {%0, %1}, %2;" : "=f"(r.x), "=f"(r.y) : "l"(v));
    return r;
}

// ---------------- generic NN SGEMM: C(MxN) = A(MxK) * B(KxN) [+bias / sigmoid-clip] ----
// MODE 0: plain (blockIdx.z unused)
// MODE 1: scores   — per-head offsets (A=Q head slice, B=K^T head slice, C=P slice)
// MODE 2: phi @ V  — per-head offsets (A=phi slice, B=V head slice, C=XO head cols)
// EPI  0: none, 1: +bias[n], 2: clamp(sigmoid(x), eps, 1-eps)
template <int BM, int BN, int BK, int TM, int TN, int MODE, int EPI>
__global__ void __launch_bounds__((BM / TM) * (BN / TN))
gemm_nn(const float* __restrict__ A, const float* __restrict__ B, float* __restrict__ C,
        const float* __restrict__ bias, int M, int N, int K,
        int lda, int ldb, int ldc) {
    constexpr int NT = (BM / TM) * (BN / TN);
    constexpr int AVEC = BM * BK / 4;
    constexpr int BVEC = BK * BN / 4;
    constexpr int APT = AVEC / NT;
    constexpr int BPT = BVEC / NT;
    static_assert(AVEC % NT == 0 && BVEC % NT == 0, "tile/thread mismatch");
    static_assert((TM % 2) == 0, "TM even for f32x2");

    __shared__ float As[BK][BM];
    __shared__ float Bs[BK][BN];

    const int z = blockIdx.z;
    if constexpr (MODE == 1) {
        A += (z >> 4) * (1024 * 1024) + (z & 15) * 64;   // Q: batch + q-head col
        B += (z & 3) * (64 * 2048) + (z >> 4) * 1024;    // K^T: kv-head rows + batch cols
        C += z << 20;                                    // P slice
    } else if constexpr (MODE == 2) {
        A += z << 20;                                    // phi slice
        B += (z >> 4) * (1024 * 256) + (z & 3) * 64;     // V: batch rows + kv-head cols
        C += (z >> 4) * (1024 * 1024) + (z & 15) * 64;   // XO: batch + q-head cols
    }

    const int tid = threadIdx.x;
    const int mBlk = blockIdx.y * BM;
    const int nBlk = blockIdx.x * BN;
    const int tn0 = (tid % (BN / TN)) * TN;
    const int tm0 = (tid / (BN / TN)) * TM;
    const int nTiles = K / BK;

    unsigned long long acc[TM / 2][TN];
#pragma unroll
    for (int i = 0; i < TM / 2; i++)
#pragma unroll
        for (int n = 0; n < TN; n++) acc[i][n] = 0ull;

    float4 aReg[APT], bReg[BPT];

    auto loadA = [&](int kt) {
#pragma unroll
        for (int q = 0; q < APT; q++) {
            int v = tid + q * NT;
            int m = v / (BK / 4);
            int kq = v % (BK / 4);
            aReg[q] = *reinterpret_cast<const float4*>(
                A + (size_t)(mBlk + m) * lda + kt * BK + kq * 4);
        }
    };
    auto loadB = [&](int kt) {
#pragma unroll
        for (int q = 0; q < BPT; q++) {
            int v = tid + q * NT;
            int k = v / (BN / 4);
            int nq = v % (BN / 4);
            bReg[q] = *reinterpret_cast<const float4*>(
                B + (size_t)(kt * BK + k) * ldb + nBlk + nq * 4);
        }
    };

    loadA(0);
    loadB(0);

    for (int kt = 0; kt < nTiles; kt++) {
#pragma unroll
        for (int q = 0; q < APT; q++) {
            int v = tid + q * NT;
            int m = v / (BK / 4);
            int kq = v % (BK / 4);
            As[kq * 4 + 0][m] = aReg[q].x;
            As[kq * 4 + 1][m] = aReg[q].y;
            As[kq * 4 + 2][m] = aReg[q].z;
            As[kq * 4 + 3][m] = aReg[q].w;
        }
#pragma unroll
        for (int q = 0; q < BPT; q++) {
            int v = tid + q * NT;
            int k = v / (BN / 4);
            int nq = v % (BN / 4);
            *reinterpret_cast<float4*>(&Bs[k][nq * 4]) = bReg[q];
        }
        __syncthreads();

        if (kt + 1 < nTiles) { loadA(kt + 1); loadB(kt + 1); }

#pragma unroll
        for (int kk = 0; kk < BK; kk++) {
            unsigned long long a2[TM / 2];
            const unsigned long long* ap =
                reinterpret_cast<const unsigned long long*>(&As[kk][tm0]);
#pragma unroll
            for (int i = 0; i < TM / 2; i++) a2[i] = ap[i];

            float bf[TN];
#pragma unroll
            for (int n = 0; n < TN; n += 4) {
                float4 b4 = *reinterpret_cast<const float4*>(&Bs[kk][tn0 + n]);
                bf[n] = b4.x; bf[n + 1] = b4.y; bf[n + 2] = b4.z; bf[n + 3] = b4.w;
            }
#pragma unroll
            for (int n = 0; n < TN; n++) {
                unsigned long long bd = dup_f32(bf[n]);
#pragma unroll
                for (int i = 0; i < TM / 2; i++)
                    acc[i][n] = fma_f32x2(a2[i], bd, acc[i][n]);
            }
        }
        __syncthreads();
    }

    // epilogue
    float bv[TN];
    if constexpr (EPI == 1) {
#pragma unroll
        for (int n = 0; n < TN; n++) bv[n] = bias[nBlk + tn0 + n];
    }
#pragma unroll
    for (int i = 0; i < TM / 2; i++) {
        float r0[TN], r1[TN];
#pragma unroll
        for (int n = 0; n < TN; n++) {
            float2 u = unpack_f32x2(acc[i][n]);
            r0[n] = u.x;
            r1[n] = u.y;
        }
#pragma unroll
        for (int n = 0; n < TN; n++) {
            if constexpr (EPI == 1) {
                r0[n] += bv[n];
                r1[n] += bv[n];
            } else if constexpr (EPI == 2) {
                r0[n] = fminf(fmaxf(1.f / (1.f + __expf(-r0[n])), EPS_P), 1.f - EPS_P);
                r1[n] = fminf(fmaxf(1.f / (1.f + __expf(-r1[n])), EPS_P), 1.f - EPS_P);
            }
        }
        size_t row0 = (size_t)(mBlk + tm0 + 2 * i) * ldc + nBlk + tn0;
#pragma unroll
        for (int n = 0; n < TN; n += 4) {
            *reinterpret_cast<float4*>(C + row0 + n) =
                make_float4(r0[n], r0[n + 1], r0[n + 2], r0[n + 3]);
            *reinterpret_cast<float4*>(C + row0 + ldc + n) =
                make_float4(r1[n], r1[n + 1], r1[n + 2], r1[n + 3]);
        }
    }
}

// ---------------- transpose: out(C x R) = in(R x C)^T ----------------
__global__ void transpose_kernel(const float* __restrict__ in, float* __restrict__ out,
                                 int R, int C) {
    __shared__ float tile[32][33];
    int c0 = blockIdx.x * 32;
    int r0 = blockIdx.y * 32;
    int x = threadIdx.x, y0 = threadIdx.y;
#pragma unroll
    for (int yy = y0; yy < 32; yy += 8) {
        int r = r0 + yy, c = c0 + x;
        if (r < R && c < C) tile[yy][x] = in[(size_t)r * C + c];
    }
    __syncthreads();
#pragma unroll
    for (int yy = y0; yy < 32; yy += 8) {
        int c = c0 + yy, r = r0 + x;
        if (r < R && c < C) out[(size_t)c * R + r] = tile[x][yy];
    }
}

// ---------------- monotonic attention scan (in place over P) ----------------
// phi[i,j] = (1 - p[i,j-1]) * phi[i,j-1] + p[i-1,j] * phi[i-1,j]; phi[0] = onehot(0).
// One block per (batch, head). 128 threads x 8 elements. Row recurrence solved by
// per-thread affine compose + warp shfl scan + 4-warp smem prefix (parity buffered).
__global__ void __launch_bounds__(128) monotonic_scan_kernel(float* __restrict__ P) {
    float* p = P + ((size_t)blockIdx.x << 20);
    const int tid = threadIdx.x;
    const int lane = tid & 31;
    const int wid = tid >> 5;
    const int j0 = tid << 3;
    __shared__ float aggA[2][4], aggB[2][4];

    float pPrev[8], phiPrev[8], cur[8];

    {
        float4 t0 = *reinterpret_cast<const float4*>(p + j0);
        float4 t1 = *reinterpret_cast<const float4*>(p + j0 + 4);
        pPrev[0] = t0.x; pPrev[1] = t0.y; pPrev[2] = t0.z; pPrev[3] = t0.w;
        pPrev[4] = t1.x; pPrev[5] = t1.y; pPrev[6] = t1.z; pPrev[7] = t1.w;
    }
#pragma unroll
    for (int x = 0; x < 8; x++) phiPrev[x] = 0.f;
    if (tid == 0) phiPrev[0] = 1.f;
    // write phi row 0 (p row 0 already consumed into registers)
    *reinterpret_cast<float4*>(p + j0) =
        make_float4(phiPrev[0], phiPrev[1], phiPrev[2], phiPrev[3]);
    *reinterpret_cast<float4*>(p + j0 + 4) =
        make_float4(phiPrev[4], phiPrev[5], phiPrev[6], phiPrev[7]);

    float curLeft;
    {
        const float* r = p + 1024;
        float4 c0 = *reinterpret_cast<const float4*>(r + j0);
        float4 c1 = *reinterpret_cast<const float4*>(r + j0 + 4);
        cur[0] = c0.x; cur[1] = c0.y; cur[2] = c0.z; cur[3] = c0.w;
        cur[4] = c1.x; cur[5] = c1.y; cur[6] = c1.z; cur[7] = c1.w;
        curLeft = (tid == 0) ? 0.f : r[j0 - 1];
    }

    for (int i = 1; i < 1024; i++) {
        // prefetch next row (hides DRAM latency behind this row's scan)
        float nxt[8];
        float nxtLeft = 0.f;
        if (i + 1 < 1024) {
            const float* r = p + (size_t)(i + 1) * 1024;
            float4 c0 = *reinterpret_cast<const float4*>(r + j0);
            float4 c1 = *reinterpret_cast<const float4*>(r + j0 + 4);
            nxt[0] = c0.x; nxt[1] = c0.y; nxt[2] = c0.z; nxt[3] = c0.w;
            nxt[4] = c1.x; nxt[5] = c1.y; nxt[6] = c1.z; nxt[7] = c1.w;
            nxtLeft = (tid == 0) ? 0.f : r[j0 - 1];
        }

        float A[8], a[8];
        A[0] = (tid == 0) ? 0.f : (1.f - curLeft);
#pragma unroll
        for (int x = 1; x < 8; x++) A[x] = 1.f - cur[x - 1];
#pragma unroll
        for (int x = 0; x < 8; x++) a[x] = phiPrev[x] * pPrev[x];

        // per-thread affine compose over 8 elements
        float Ac = A[0], bc = a[0];
#pragma unroll
        for (int x = 1; x < 8; x++) {
            bc = fmaf(bc, A[x], a[x]);
            Ac *= A[x];
        }

        // warp inclusive scan of (A,b)
        float sA = Ac, sB = bc;
#pragma unroll
        for (int d = 1; d < 32; d <<= 1) {
            float oA = __shfl_up_sync(0xffffffffu, sA, d);
            float oB = __shfl_up_sync(0xffffffffu, sB, d);
            if (lane >= d) {
                sB = fmaf(oB, sA, sB);
                sA = oA * sA;
            }
        }

        const int par = i & 1;
        if (lane == 31) {
            aggA[par][wid] = sA;
            aggB[par][wid] = sB;
        }
        __syncthreads();

        // prefix over preceding warps (y before this warp's first element)
        float yw = 0.f;
#pragma unroll
        for (int w = 0; w < 3; w++)
            if (w < wid) yw = fmaf(yw, aggA[par][w], aggB[par][w]);

        // exclusive within warp
        float eA = __shfl_up_sync(0xffffffffu, sA, 1);
        float eB = __shfl_up_sync(0xffffffffu, sB, 1);
        if (lane == 0) { eA = 1.f; eB = 0.f; }
        float y = fmaf(yw, eA, eB);  // phi value just before this thread's chunk

        // serial fixup -> phi row i values
#pragma unroll
        for (int x = 0; x < 8; x++) {
            y = fmaf(A[x], y, a[x]);
            phiPrev[x] = y;
        }

        float* orow = p + (size_t)i * 1024 + j0;
        *reinterpret_cast<float4*>(orow) =
            make_float4(phiPrev[0], phiPrev[1], phiPrev[2], phiPrev[3]);
        *reinterpret_cast<float4*>(orow + 4) =
            make_float4(phiPrev[4], phiPrev[5], phiPrev[6], phiPrev[7]);

#pragma unroll
        for (int x = 0; x < 8; x++) pPrev[x] = cur[x];
        if (i + 1 < 1024) {
#pragma unroll
            for (int x = 0; x < 8; x++) cur[x] = nxt[x];
            curLeft = nxtLeft;
        }
    }
}

// ---------------- launch ----------------
extern "C" void kernel_launch(void* const* d_in, const int* in_sizes, int n_in,
                              void* d_out, int out_size) {
    (void)in_sizes; (void)n_in; (void)out_size;
    const float* query = (const float*)d_in[0];
    const float* key   = (const float*)d_in[1];
    const float* value = (const float*)d_in[2];
    const float* Win   = (const float*)d_in[3];
    const float* bin   = (const float*)d_in[4];
    const float* Wout  = (const float*)d_in[5];
    const float* bout  = (const float*)d_in[6];
    float* out = (float*)d_out;

    float *WinT, *WoutT, *Q, *Kb, *Vb, *KT, *P, *XO;
    cudaGetSymbolAddress((void**)&WinT, g_WinT);
    cudaGetSymbolAddress((void**)&WoutT, g_WoutT);
    cudaGetSymbolAddress((void**)&Q, g_Q);
    cudaGetSymbolAddress((void**)&Kb, g_K);
    cudaGetSymbolAddress((void**)&Vb, g_V);
    cudaGetSymbolAddress((void**)&KT, g_KT);
    cudaGetSymbolAddress((void**)&P, g_P);
    cudaGetSymbolAddress((void**)&XO, g_XO);

    dim3 tb(32, 8);
    // weight transposes (W is (out,in); we need (in,out) for NN GEMM)
    transpose_kernel<<<dim3(1024 / 32, 1536 / 32), tb>>>(Win, WinT, 1536, 1024);
    transpose_kernel<<<dim3(1024 / 32, 1024 / 32), tb>>>(Wout, WoutT, 1024, 1024);

    // Q projection: (2048x1024) = query (2048x1024) @ WinT[:, 0:1024]
    gemm_nn<128, 128, 16, 8, 8, 0, 1><<<dim3(8, 16, 1), 256>>>(
        query, WinT, Q, bin, 2048, 1024, 1024, 1024, 1536, 1024);
    // K projection: (2048x256) = key @ WinT[:, 1024:1280]
    gemm_nn<64, 128, 16, 8, 8, 0, 1><<<dim3(2, 32, 1), 128>>>(
        key, WinT + 1024, Kb, bin + 1024, 2048, 256, 1024, 1024, 1536, 256);
    // V projection: (2048x256) = value @ WinT[:, 1280:1536]
    gemm_nn<64, 128, 16, 8, 8, 0, 1><<<dim3(2, 32, 1), 128>>>(
        value, WinT + 1280, Vb, bin + 1280, 2048, 256, 1024, 1024, 1536, 256);

    // K transpose to (embed x token) for NN score GEMM
    transpose_kernel<<<dim3(256 / 32, 2048 / 32), tb>>>(Kb, KT, 2048, 256);

    // scores per head: P = clamp(sigmoid(Qh @ Kh^T), eps, 1-eps); 32 heads in grid.z
    gemm_nn<128, 128, 16, 8, 8, 1, 2><<<dim3(8, 8, 32), 256>>>(
        Q, KT, P, nullptr, 1024, 1024, 64, 1024, 2048, 1024);

    // monotonic attention recurrence (in place: P -> phi)
    monotonic_scan_kernel<<<32, 128>>>(P);

    // O = phi @ V per head, scattered into XO (token-major, per-head columns)
    gemm_nn<128, 64, 16, 8, 8, 2, 0><<<dim3(1, 8, 32), 128>>>(
        P, Vb, XO, nullptr, 1024, 64, 1024, 1024, 256, 1024);

    // output projection
    gemm_nn<128, 128, 16, 8, 8, 0, 1><<<dim3(8, 16, 1), 256>>>(
        XO, WoutT, out, bout, 2048, 1024, 1024, 1024, 1024, 1024);
}

// round 13
// speedup vs baseline: 1.0252x; 1.0252x over previous
#include <cuda_runtime.h>
#include <cstdint>

#define EPS_P 0.001f

// ---------------- scratch (device globals: no allocation, graph-safe) ----------------
__device__ float g_WinT[1024 * 1536];   // in_proj_weight^T  (K=1024 x N=1536)
__device__ float g_WoutT[1024 * 1024];  // out_proj_weight^T (1024 x 1024)
__device__ float g_Q[2048 * 1024];      // projected queries
__device__ float g_K[2048 * 256];       // projected keys
__device__ float g_V[2048 * 256];       // projected values
__device__ float g_KT[256 * 2048];      // keys transposed (embed x token)
__device__ float g_P[32 * 1024 * 1024]; // sigmoid probs -> phi (in place)
__device__ float g_XO[2048 * 1024];     // attention output (token-major, per-head cols)

// ---------------- f32x2 packed-FMA helpers (FFMA2 only reachable via PTX) ----------------
__device__ __forceinline__ unsigned long long fma_f32x2(unsigned long long a,
                                                        unsigned long long b,
                                                        unsigned long long c) {
    unsigned long long d;
    asm("fma.rn.f32x2 %0, %1, %2, %3;" : "=l"(d) : "l"(a), "l"(b), "l"(c));
    return d;
}
__device__ __forceinline__ unsigned long long dup_f32(float x) {
    unsigned long long d;
    asm("mov.b64 %0, {%1, %1};" : "=l"(d) : "f"(x));
    return d;
}
__device__ __forceinline__ float2 unpack_f32x2(unsigned long long v) {
    float2 r;
    asm("mov.b64 {%0, %1}, %2;" : "=f"(r.x), "=f"(r.y) : "l"(v));
    return r;
}

// ---------------- generic NN SGEMM: C(MxN) = A(MxK) * B(KxN) [+bias / sigmoid-clip] ----
// MODE 0: plain (blockIdx.z unused)
// MODE 1: scores   — per-head offsets (A=Q head slice, B=K^T head slice, C=P slice)
// MODE 2: phi @ V  — per-head offsets (A=phi slice, B=V head slice, C=XO head cols)
// EPI  0: none, 1: +bias[n], 2: clamp(sigmoid(x), eps, 1-eps)
template <int BM, int BN, int BK, int TM, int TN, int MODE, int EPI>
__global__ void __launch_bounds__((BM / TM) * (BN / TN))
gemm_nn(const float* __restrict__ A, const float* __restrict__ B, float* __restrict__ C,
        const float* __restrict__ bias, int M, int N, int K,
        int lda, int ldb, int ldc) {
    constexpr int NT = (BM / TM) * (BN / TN);
    constexpr int AVEC = BM * BK / 4;
    constexpr int BVEC = BK * BN / 4;
    constexpr int APT = AVEC / NT;
    constexpr int BPT = BVEC / NT;
    static_assert(AVEC % NT == 0 && BVEC % NT == 0, "tile/thread mismatch");
    static_assert((TM % 2) == 0, "TM even for f32x2");

    __shared__ float As[BK][BM];
    __shared__ float Bs[BK][BN];

    const int z = blockIdx.z;
    if constexpr (MODE == 1) {
        A += (z >> 4) * (1024 * 1024) + (z & 15) * 64;   // Q: batch + q-head col
        B += (z & 3) * (64 * 2048) + (z >> 4) * 1024;    // K^T: kv-head rows + batch cols
        C += z << 20;                                    // P slice
    } else if constexpr (MODE == 2) {
        A += z << 20;                                    // phi slice
        B += (z >> 4) * (1024 * 256) + (z & 3) * 64;     // V: batch rows + kv-head cols
        C += (z >> 4) * (1024 * 1024) + (z & 15) * 64;   // XO: batch + q-head cols
    }

    const int tid = threadIdx.x;
    const int mBlk = blockIdx.y * BM;
    const int nBlk = blockIdx.x * BN;
    const int tn0 = (tid % (BN / TN)) * TN;
    const int tm0 = (tid / (BN / TN)) * TM;
    const int nTiles = K / BK;

    unsigned long long acc[TM / 2][TN];
#pragma unroll
    for (int i = 0; i < TM / 2; i++)
#pragma unroll
        for (int n = 0; n < TN; n++) acc[i][n] = 0ull;

    float4 aReg[APT], bReg[BPT];

    auto loadA = [&](int kt) {
#pragma unroll
        for (int q = 0; q < APT; q++) {
            int v = tid + q * NT;
            int m = v / (BK / 4);
            int kq = v % (BK / 4);
            aReg[q] = *reinterpret_cast<const float4*>(
                A + (size_t)(mBlk + m) * lda + kt * BK + kq * 4);
        }
    };
    auto loadB = [&](int kt) {
#pragma unroll
        for (int q = 0; q < BPT; q++) {
            int v = tid + q * NT;
            int k = v / (BN / 4);
            int nq = v % (BN / 4);
            bReg[q] = *reinterpret_cast<const float4*>(
                B + (size_t)(kt * BK + k) * ldb + nBlk + nq * 4);
        }
    };

    loadA(0);
    loadB(0);

    for (int kt = 0; kt < nTiles; kt++) {
#pragma unroll
        for (int q = 0; q < APT; q++) {
            int v = tid + q * NT;
            int m = v / (BK / 4);
            int kq = v % (BK / 4);
            As[kq * 4 + 0][m] = aReg[q].x;
            As[kq * 4 + 1][m] = aReg[q].y;
            As[kq * 4 + 2][m] = aReg[q].z;
            As[kq * 4 + 3][m] = aReg[q].w;
        }
#pragma unroll
        for (int q = 0; q < BPT; q++) {
            int v = tid + q * NT;
            int k = v / (BN / 4);
            int nq = v % (BN / 4);
            *reinterpret_cast<float4*>(&Bs[k][nq * 4]) = bReg[q];
        }
        __syncthreads();

        if (kt + 1 < nTiles) { loadA(kt + 1); loadB(kt + 1); }

#pragma unroll
        for (int kk = 0; kk < BK; kk++) {
            unsigned long long a2[TM / 2];
            const unsigned long long* ap =
                reinterpret_cast<const unsigned long long*>(&As[kk][tm0]);
#pragma unroll
            for (int i = 0; i < TM / 2; i++) a2[i] = ap[i];

            float bf[TN];
#pragma unroll
            for (int n = 0; n < TN; n += 4) {
                float4 b4 = *reinterpret_cast<const float4*>(&Bs[kk][tn0 + n]);
                bf[n] = b4.x; bf[n + 1] = b4.y; bf[n + 2] = b4.z; bf[n + 3] = b4.w;
            }
#pragma unroll
            for (int n = 0; n < TN; n++) {
                unsigned long long bd = dup_f32(bf[n]);
#pragma unroll
                for (int i = 0; i < TM / 2; i++)
                    acc[i][n] = fma_f32x2(a2[i], bd, acc[i][n]);
            }
        }
        __syncthreads();
    }

    // epilogue
    float bv[TN];
    if constexpr (EPI == 1) {
#pragma unroll
        for (int n = 0; n < TN; n++) bv[n] = bias[nBlk + tn0 + n];
    }
#pragma unroll
    for (int i = 0; i < TM / 2; i++) {
        float r0[TN], r1[TN];
#pragma unroll
        for (int n = 0; n < TN; n++) {
            float2 u = unpack_f32x2(acc[i][n]);
            r0[n] = u.x;
            r1[n] = u.y;
        }
#pragma unroll
        for (int n = 0; n < TN; n++) {
            if constexpr (EPI == 1) {
                r0[n] += bv[n];
                r1[n] += bv[n];
            } else if constexpr (EPI == 2) {
                r0[n] = fminf(fmaxf(1.f / (1.f + __expf(-r0[n])), EPS_P), 1.f - EPS_P);
                r1[n] = fminf(fmaxf(1.f / (1.f + __expf(-r1[n])), EPS_P), 1.f - EPS_P);
            }
        }
        size_t row0 = (size_t)(mBlk + tm0 + 2 * i) * ldc + nBlk + tn0;
#pragma unroll
        for (int n = 0; n < TN; n += 4) {
            *reinterpret_cast<float4*>(C + row0 + n) =
                make_float4(r0[n], r0[n + 1], r0[n + 2], r0[n + 3]);
            *reinterpret_cast<float4*>(C + row0 + ldc + n) =
                make_float4(r1[n], r1[n + 1], r1[n + 2], r1[n + 3]);
        }
    }
}

// ---------------- transpose: out(C x R) = in(R x C)^T ----------------
__global__ void transpose_kernel(const float* __restrict__ in, float* __restrict__ out,
                                 int R, int C) {
    __shared__ float tile[32][33];
    int c0 = blockIdx.x * 32;
    int r0 = blockIdx.y * 32;
    int x = threadIdx.x, y0 = threadIdx.y;
#pragma unroll
    for (int yy = y0; yy < 32; yy += 8) {
        int r = r0 + yy, c = c0 + x;
        if (r < R && c < C) tile[yy][x] = in[(size_t)r * C + c];
    }
    __syncthreads();
#pragma unroll
    for (int yy = y0; yy < 32; yy += 8) {
        int c = c0 + yy, r = r0 + x;
        if (r < R && c < C) out[(size_t)c * R + r] = tile[x][yy];
    }
}

// ---------------- monotonic attention scan (in place over P) ----------------
// phi[i,j] = (1 - p[i,j-1]) * phi[i,j-1] + p[i-1,j] * phi[i-1,j]; phi[0] = onehot(0).
// One block per (batch, head). 128 threads x 8 elements. Row recurrence solved by
// per-thread affine compose + warp shfl scan + 4-warp smem prefix (parity buffered).
__global__ void __launch_bounds__(128) monotonic_scan_kernel(float* __restrict__ P) {
    float* p = P + ((size_t)blockIdx.x << 20);
    const int tid = threadIdx.x;
    const int lane = tid & 31;
    const int wid = tid >> 5;
    const int j0 = tid << 3;
    __shared__ float aggA[2][4], aggB[2][4];

    float pPrev[8], phiPrev[8], cur[8];

    {
        float4 t0 = *reinterpret_cast<const float4*>(p + j0);
        float4 t1 = *reinterpret_cast<const float4*>(p + j0 + 4);
        pPrev[0] = t0.x; pPrev[1] = t0.y; pPrev[2] = t0.z; pPrev[3] = t0.w;
        pPrev[4] = t1.x; pPrev[5] = t1.y; pPrev[6] = t1.z; pPrev[7] = t1.w;
    }
#pragma unroll
    for (int x = 0; x < 8; x++) phiPrev[x] = 0.f;
    if (tid == 0) phiPrev[0] = 1.f;
    // write phi row 0 (p row 0 already consumed into registers)
    *reinterpret_cast<float4*>(p + j0) =
        make_float4(phiPrev[0], phiPrev[1], phiPrev[2], phiPrev[3]);
    *reinterpret_cast<float4*>(p + j0 + 4) =
        make_float4(phiPrev[4], phiPrev[5], phiPrev[6], phiPrev[7]);

    float curLeft;
    {
        const float* r = p + 1024;
        float4 c0 = *reinterpret_cast<const float4*>(r + j0);
        float4 c1 = *reinterpret_cast<const float4*>(r + j0 + 4);
        cur[0] = c0.x; cur[1] = c0.y; cur[2] = c0.z; cur[3] = c0.w;
        cur[4] = c1.x; cur[5] = c1.y; cur[6] = c1.z; cur[7] = c1.w;
        curLeft = (tid == 0) ? 0.f : r[j0 - 1];
    }

    for (int i = 1; i < 1024; i++) {
        // prefetch next row (hides DRAM latency behind this row's scan)
        float nxt[8];
        float nxtLeft = 0.f;
        if (i + 1 < 1024) {
            const float* r = p + (size_t)(i + 1) * 1024;
            float4 c0 = *reinterpret_cast<const float4*>(r + j0);
            float4 c1 = *reinterpret_cast<const float4*>(r + j0 + 4);
            nxt[0] = c0.x; nxt[1] = c0.y; nxt[2] = c0.z; nxt[3] = c0.w;
            nxt[4] = c1.x; nxt[5] = c1.y; nxt[6] = c1.z; nxt[7] = c1.w;
            nxtLeft = (tid == 0) ? 0.f : r[j0 - 1];
        }

        float A[8], a[8];
        A[0] = (tid == 0) ? 0.f : (1.f - curLeft);
#pragma unroll
        for (int x = 1; x < 8; x++) A[x] = 1.f - cur[x - 1];
#pragma unroll
        for (int x = 0; x < 8; x++) a[x] = phiPrev[x] * pPrev[x];

        // per-thread affine compose over 8 elements
        float Ac = A[0], bc = a[0];
#pragma unroll
        for (int x = 1; x < 8; x++) {
            bc = fmaf(bc, A[x], a[x]);
            Ac *= A[x];
        }

        // warp inclusive scan of (A,b)
        float sA = Ac, sB = bc;
#pragma unroll
        for (int d = 1; d < 32; d <<= 1) {
            float oA = __shfl_up_sync(0xffffffffu, sA, d);
            float oB = __shfl_up_sync(0xffffffffu, sB, d);
            if (lane >= d) {
                sB = fmaf(oB, sA, sB);
                sA = oA * sA;
            }
        }

        const int par = i & 1;
        if (lane == 31) {
            aggA[par][wid] = sA;
            aggB[par][wid] = sB;
        }
        __syncthreads();

        // prefix over preceding warps (y before this warp's first element)
        float yw = 0.f;
#pragma unroll
        for (int w = 0; w < 3; w++)
            if (w < wid) yw = fmaf(yw, aggA[par][w], aggB[par][w]);

        // exclusive within warp
        float eA = __shfl_up_sync(0xffffffffu, sA, 1);
        float eB = __shfl_up_sync(0xffffffffu, sB, 1);
        if (lane == 0) { eA = 1.f; eB = 0.f; }
        float y = fmaf(yw, eA, eB);  // phi value just before this thread's chunk

        // serial fixup -> phi row i values
#pragma unroll
        for (int x = 0; x < 8; x++) {
            y = fmaf(A[x], y, a[x]);
            phiPrev[x] = y;
        }

        float* orow = p + (size_t)i * 1024 + j0;
        *reinterpret_cast<float4*>(orow) =
            make_float4(phiPrev[0], phiPrev[1], phiPrev[2], phiPrev[3]);
        *reinterpret_cast<float4*>(orow + 4) =
            make_float4(phiPrev[4], phiPrev[5], phiPrev[6], phiPrev[7]);

#pragma unroll
        for (int x = 0; x < 8; x++) pPrev[x] = cur[x];
        if (i + 1 < 1024) {
#pragma unroll
            for (int x = 0; x < 8; x++) cur[x] = nxt[x];
            curLeft = nxtLeft;
        }
    }
}

// ---------------- launch ----------------
extern "C" void kernel_launch(void* const* d_in, const int* in_sizes, int n_in,
                              void* d_out, int out_size) {
    (void)in_sizes; (void)n_in; (void)out_size;
    const float* query = (const float*)d_in[0];
    const float* key   = (const float*)d_in[1];
    const float* value = (const float*)d_in[2];
    const float* Win   = (const float*)d_in[3];
    const float* bin   = (const float*)d_in[4];
    const float* Wout  = (const float*)d_in[5];
    const float* bout  = (const float*)d_in[6];
    float* out = (float*)d_out;

    float *WinT, *WoutT, *Q, *Kb, *Vb, *KT, *P, *XO;
    cudaGetSymbolAddress((void**)&WinT, g_WinT);
    cudaGetSymbolAddress((void**)&WoutT, g_WoutT);
    cudaGetSymbolAddress((void**)&Q, g_Q);
    cudaGetSymbolAddress((void**)&Kb, g_K);
    cudaGetSymbolAddress((void**)&Vb, g_V);
    cudaGetSymbolAddress((void**)&KT, g_KT);
    cudaGetSymbolAddress((void**)&P, g_P);
    cudaGetSymbolAddress((void**)&XO, g_XO);

    dim3 tb(32, 8);
    // weight transposes (W is (out,in); we need (in,out) for NN GEMM)
    transpose_kernel<<<dim3(1024 / 32, 1536 / 32), tb>>>(Win, WinT, 1536, 1024);
    transpose_kernel<<<dim3(1024 / 32, 1024 / 32), tb>>>(Wout, WoutT, 1024, 1024);

    // Q projection: (2048x1024) = query (2048x1024) @ WinT[:, 0:1024]
    gemm_nn<128, 128, 16, 8, 8, 0, 1><<<dim3(8, 16, 1), 256>>>(
        query, WinT, Q, bin, 2048, 1024, 1024, 1024, 1536, 1024);
    // K projection: (2048x256) = key @ WinT[:, 1024:1280]
    gemm_nn<64, 128, 16, 8, 8, 0, 1><<<dim3(2, 32, 1), 128>>>(
        key, WinT + 1024, Kb, bin + 1024, 2048, 256, 1024, 1024, 1536, 256);
    // V projection: (2048x256) = value @ WinT[:, 1280:1536]
    gemm_nn<64, 128, 16, 8, 8, 0, 1><<<dim3(2, 32, 1), 128>>>(
        value, WinT + 1280, Vb, bin + 1280, 2048, 256, 1024, 1024, 1536, 256);

    // K transpose to (embed x token) for NN score GEMM
    transpose_kernel<<<dim3(256 / 32, 2048 / 32), tb>>>(Kb, KT, 2048, 256);

    // scores per head: P = clamp(sigmoid(Qh @ Kh^T), eps, 1-eps); 32 heads in grid.z
    gemm_nn<128, 128, 16, 8, 8, 1, 2><<<dim3(8, 8, 32), 256>>>(
        Q, KT, P, nullptr, 1024, 1024, 64, 1024, 2048, 1024);

    // monotonic attention recurrence (in place: P -> phi)
    monotonic_scan_kernel<<<32, 128>>>(P);

    // O = phi @ V per head, scattered into XO (token-major, per-head columns)
    gemm_nn<128, 64, 16, 8, 8, 2, 0><<<dim3(1, 8, 32), 128>>>(
        P, Vb, XO, nullptr, 1024, 64, 1024, 1024, 256, 1024);

    // output projection
    gemm_nn<128, 128, 16, 8, 8, 0, 1><<<dim3(8, 16, 1), 256>>>(
        XO, WoutT, out, bout, 2048, 1024, 1024, 1024, 1024, 1024);
}

// round 16
// speedup vs baseline: 1.4933x; 1.4566x over previous
#include <cuda_runtime.h>
#include <cuda_bf16.h>
#include <cstdint>

#define EPS_P 0.001f

// ---------------- scratch (device globals: no allocation, graph-safe) ----------------
__device__ float g_Q[2048 * 1024];      // projected queries
__device__ float g_K[2048 * 256];       // projected keys
__device__ float g_V[2048 * 256];       // projected values
__device__ float g_VT[256 * 2048];      // values transposed (embed x token)
__device__ float g_P[32 * 1024 * 1024]; // sigmoid probs -> phi (in place)
__device__ float g_XO[2048 * 1024];     // attention output (token-major, per-head cols)

// ---------------- helpers ----------------
__device__ __forceinline__ uint32_t smem_u32(const void* p) {
    uint32_t a;
    asm("{ .reg .u64 t; cvta.to.shared.u64 t, %1; cvt.u32.u64 %0, t; }" : "=r"(a) : "l"(p));
    return a;
}
__device__ __forceinline__ uint32_t sw128(uint32_t off) { return off ^ ((off >> 3) & 0x70); }

__device__ __forceinline__ void ldsm_x4(uint32_t (&r)[4], uint32_t addr) {
    asm volatile("ldmatrix.sync.aligned.m8n8.x4.shared.b16 {%0,%1,%2,%3}, [%4];"
                 : "=r"(r[0]), "=r"(r[1]), "=r"(r[2]), "=r"(r[3]) : "r"(addr));
}
// NON-trans x2: for B stored (N,K) row-major (k-contiguous), this yields exactly the
// m16n8k16 "col-major B" fragment b(l) = B_nk[l/4][2*(l%4)]. (.trans was the R15 bug.)
__device__ __forceinline__ void ldsm_x2(uint32_t (&r)[2], uint32_t addr) {
    asm volatile("ldmatrix.sync.aligned.m8n8.x2.shared.b16 {%0,%1}, [%2];"
                 : "=r"(r[0]), "=r"(r[1]) : "r"(addr));
}
__device__ __forceinline__ void mma16816(float (&c)[4], const uint32_t (&a)[4],
                                         const uint32_t (&b)[2]) {
    asm volatile(
        "mma.sync.aligned.m16n8k16.row.col.f32.bf16.bf16.f32 "
        "{%0,%1,%2,%3}, {%4,%5,%6,%7}, {%8,%9}, {%0,%1,%2,%3};"
        : "+f"(c[0]), "+f"(c[1]), "+f"(c[2]), "+f"(c[3])
        : "r"(a[0]), "r"(a[1]), "r"(a[2]), "r"(a[3]), "r"(b[0]), "r"(b[1]));
}

// fp32 -> (bf16 hi, bf16 lo residual) pair conversion, packs two elements.
__device__ __forceinline__ void cvt2(float a, float b, uint32_t& h, uint32_t& l) {
    __nv_bfloat16 ha = __float2bfloat16_rn(a);
    __nv_bfloat16 hb = __float2bfloat16_rn(b);
    float ra = a - __bfloat162float(ha);
    float rb = b - __bfloat162float(hb);
    __nv_bfloat162 H;
    H.x = ha; H.y = hb;
    __nv_bfloat162 L = __floats2bfloat162_rn(ra, rb);
    h = *reinterpret_cast<uint32_t*>(&H);
    l = *reinterpret_cast<uint32_t*>(&L);
}

// ---------------- warp-MMA split-precision GEMM ----------------
// C(m,n) = sum_k A[m,k] * B[n,k]   (B operand is (N,K) row-major -> no transposes!)
// Split: A=Ah+Al, B=Bh+Bl (bf16 hi/lo); D += AhBh + AhBl + AlBh (fp32 accum).
// Block tile M=128 x BN, K-chunk=64, register-staged global prefetch.
// MODE 0: plain. MODE 1: scores (z=b*16+qh; A=Q slice, B=Kproj slice, C=P slice).
// MODE 2: phi@V  (A=phi slice, B=VT slice, C=XO head cols).
// MODE 3: fused K/V projection (z&1 selects key/value via A2/C2; B/bias offset in Win).
// EPI 0: none. 1: +bias[n]. 2: clamp(sigmoid, eps, 1-eps).
template <int BN, int WARPS_M, int WARPS_N, int MODE, int EPI>
__global__ void __launch_bounds__(32 * WARPS_M * WARPS_N)
gemm_tc(const float* __restrict__ A, const float* __restrict__ B, float* __restrict__ C,
        const float* __restrict__ bias, const float* __restrict__ A2, float* __restrict__ C2,
        int K, int lda, int ldb, int ldc) {
    constexpr int NT = 32 * WARPS_M * WARPS_N;
    constexpr int WM = 128 / WARPS_M;
    constexpr int WN = BN / WARPS_N;
    constexpr int MSUB = WM / 16;
    constexpr int NSUB = WN / 8;
    constexpr int APT = 128 * 16 / NT;   // float4s of A tile per thread
    constexpr int BPT = BN * 16 / NT;    // float4s of B tile per thread
    constexpr int ABYTES = 128 * 128;    // one A bf16 tile (128 x 64 @128B rows)
    constexpr int BBYTES = BN * 128;
    // smem layout: Ah | Al | Bh | Bl
    extern __shared__ char smem[];

    const int tid = threadIdx.x;
    const int wid = tid >> 5;
    const int lane = tid & 31;
    const int warp_m = wid % WARPS_M;
    const int warp_n = wid / WARPS_M;
    const uint32_t sb = smem_u32(smem);

    const int z = blockIdx.z;
    if constexpr (MODE == 1) {
        A += (size_t)(z >> 4) * (1024 * 1024) + (z & 15) * 64;  // Q: batch + q-head cols
        B += (size_t)(z >> 4) * (1024 * 256) + (z & 3) * 64;    // Kproj: batch rows + kv-head cols
        C += (size_t)z << 20;                                   // P slice
    } else if constexpr (MODE == 2) {
        A += (size_t)z << 20;                                   // phi slice
        B += (size_t)(z & 3) * 64 * 2048 + (z >> 4) * 1024;     // VT: kv-head rows + batch cols
        C += (size_t)(z >> 4) * (1024 * 1024) + (z & 15) * 64;  // XO: batch + q-head cols
    } else if constexpr (MODE == 3) {
        if (z & 1) { A = A2; C = C2; }
        B += (size_t)(1024 + (z & 1) * 256) * 1024;             // Win K-rows / V-rows
        bias += 1024 + (z & 1) * 256;
    }

    const int mBlk = blockIdx.y * 128;
    const int nBlk = blockIdx.x * BN;
    const int nK = K >> 6;

    float acc[MSUB][NSUB][4];
#pragma unroll
    for (int ms = 0; ms < MSUB; ms++)
#pragma unroll
        for (int ns = 0; ns < NSUB; ns++)
#pragma unroll
            for (int i = 0; i < 4; i++) acc[ms][ns][i] = 0.f;

    float4 aReg[APT], bReg[BPT];
    auto loadA = [&](int kt) {
#pragma unroll
        for (int q = 0; q < APT; q++) {
            int v = tid + q * NT;
            int r = v >> 4, kq = v & 15;
            aReg[q] = *reinterpret_cast<const float4*>(
                A + (size_t)(mBlk + r) * lda + kt * 64 + kq * 4);
        }
    };
    auto loadB = [&](int kt) {
#pragma unroll
        for (int q = 0; q < BPT; q++) {
            int v = tid + q * NT;
            int n = v >> 4, kq = v & 15;
            bReg[q] = *reinterpret_cast<const float4*>(
                B + (size_t)(nBlk + n) * ldb + kt * 64 + kq * 4);
        }
    };

    // ldmatrix address bases (byte offsets within a tile, swizzle applied per k-step)
    uint32_t aRow[MSUB], bRow[NSUB];
#pragma unroll
    for (int ms = 0; ms < MSUB; ms++)
        aRow[ms] = (uint32_t)((warp_m * WM + ms * 16 + (lane & 15)) * 128 + (lane & 16));
#pragma unroll
    for (int ns = 0; ns < NSUB; ns++)
        bRow[ns] = (uint32_t)((warp_n * WN + ns * 8 + (lane & 7)) * 128 +
                              (((lane >> 3) & 1) << 4));

    loadA(0);
    loadB(0);

    for (int kt = 0; kt < nK; kt++) {
        // stage: convert fp32 regs -> bf16 hi/lo, store SW128-swizzled
#pragma unroll
        for (int q = 0; q < APT; q++) {
            int v = tid + q * NT;
            int r = v >> 4, kq = v & 15;
            uint32_t h0, l0, h1, l1;
            cvt2(aReg[q].x, aReg[q].y, h0, l0);
            cvt2(aReg[q].z, aReg[q].w, h1, l1);
            uint32_t off = sw128((uint32_t)(r * 128 + kq * 8));
            *reinterpret_cast<uint2*>(smem + off) = make_uint2(h0, h1);
            *reinterpret_cast<uint2*>(smem + ABYTES + off) = make_uint2(l0, l1);
        }
#pragma unroll
        for (int q = 0; q < BPT; q++) {
            int v = tid + q * NT;
            int n = v >> 4, kq = v & 15;
            uint32_t h0, l0, h1, l1;
            cvt2(bReg[q].x, bReg[q].y, h0, l0);
            cvt2(bReg[q].z, bReg[q].w, h1, l1);
            uint32_t off = sw128((uint32_t)(n * 128 + kq * 8));
            *reinterpret_cast<uint2*>(smem + 2 * ABYTES + off) = make_uint2(h0, h1);
            *reinterpret_cast<uint2*>(smem + 2 * ABYTES + BBYTES + off) = make_uint2(l0, l1);
        }
        __syncthreads();

        if (kt + 1 < nK) { loadA(kt + 1); loadB(kt + 1); }

#pragma unroll
        for (int ks = 0; ks < 4; ks++) {
            uint32_t afh[MSUB][4], afl[MSUB][4], bfh[NSUB][2], bfl[NSUB][2];
#pragma unroll
            for (int ms = 0; ms < MSUB; ms++) {
                uint32_t off = sw128(aRow[ms] + ks * 32);
                ldsm_x4(afh[ms], sb + off);
                ldsm_x4(afl[ms], sb + ABYTES + off);
            }
#pragma unroll
            for (int ns = 0; ns < NSUB; ns++) {
                uint32_t off = sw128(bRow[ns] + ks * 32);
                ldsm_x2(bfh[ns], sb + 2 * ABYTES + off);
                ldsm_x2(bfl[ns], sb + 2 * ABYTES + BBYTES + off);
            }
#pragma unroll
            for (int ms = 0; ms < MSUB; ms++)
#pragma unroll
                for (int ns = 0; ns < NSUB; ns++) {
                    mma16816(acc[ms][ns], afh[ms], bfh[ns]);
                    mma16816(acc[ms][ns], afh[ms], bfl[ns]);
                    mma16816(acc[ms][ns], afl[ms], bfh[ns]);
                }
        }
        __syncthreads();
    }

    // epilogue: c0=(g,2q) c1=(g,2q+1) c2=(g+8,2q) c3=(g+8,2q+1)
    const int g = lane >> 2;
    const int qq = lane & 3;
#pragma unroll
    for (int ms = 0; ms < MSUB; ms++) {
#pragma unroll
        for (int ns = 0; ns < NSUB; ns++) {
            int r0 = mBlk + warp_m * WM + ms * 16 + g;
            int c0 = nBlk + warp_n * WN + ns * 8 + qq * 2;
            float v[4] = {acc[ms][ns][0], acc[ms][ns][1], acc[ms][ns][2], acc[ms][ns][3]};
            if constexpr (EPI == 1) {
                float b0 = __ldg(&bias[c0]);
                float b1 = __ldg(&bias[c0 + 1]);
                v[0] += b0; v[1] += b1; v[2] += b0; v[3] += b1;
            } else if constexpr (EPI == 2) {
#pragma unroll
                for (int i = 0; i < 4; i++) {
                    float s = 1.f / (1.f + __expf(-v[i]));
                    v[i] = fminf(fmaxf(s, EPS_P), 1.f - EPS_P);
                }
            }
            *reinterpret_cast<float2*>(C + (size_t)r0 * ldc + c0) = make_float2(v[0], v[1]);
            *reinterpret_cast<float2*>(C + (size_t)(r0 + 8) * ldc + c0) = make_float2(v[2], v[3]);
        }
    }
}

// ---------------- transpose: out(C x R) = in(R x C)^T ----------------
__global__ void transpose_kernel(const float* __restrict__ in, float* __restrict__ out,
                                 int R, int C) {
    __shared__ float tile[32][33];
    int c0 = blockIdx.x * 32;
    int r0 = blockIdx.y * 32;
    int x = threadIdx.x, y0 = threadIdx.y;
#pragma unroll
    for (int yy = y0; yy < 32; yy += 8) {
        int r = r0 + yy, c = c0 + x;
        if (r < R && c < C) tile[yy][x] = in[(size_t)r * C + c];
    }
    __syncthreads();
#pragma unroll
    for (int yy = y0; yy < 32; yy += 8) {
        int c = c0 + yy, r = r0 + x;
        if (r < R && c < C) out[(size_t)c * R + r] = tile[x][yy];
    }
}

// ---------------- monotonic attention scan (in place over P) ----------------
// phi[i,j] = (1 - p[i,j-1]) * phi[i,j-1] + p[i-1,j] * phi[i-1,j]; phi[0] = onehot(0).
__global__ void __launch_bounds__(128) monotonic_scan_kernel(float* __restrict__ P) {
    float* p = P + ((size_t)blockIdx.x << 20);
    const int tid = threadIdx.x;
    const int lane = tid & 31;
    const int wid = tid >> 5;
    const int j0 = tid << 3;
    __shared__ float aggA[2][4], aggB[2][4];

    float pPrev[8], phiPrev[8], cur[8];

    {
        float4 t0 = *reinterpret_cast<const float4*>(p + j0);
        float4 t1 = *reinterpret_cast<const float4*>(p + j0 + 4);
        pPrev[0] = t0.x; pPrev[1] = t0.y; pPrev[2] = t0.z; pPrev[3] = t0.w;
        pPrev[4] = t1.x; pPrev[5] = t1.y; pPrev[6] = t1.z; pPrev[7] = t1.w;
    }
#pragma unroll
    for (int x = 0; x < 8; x++) phiPrev[x] = 0.f;
    if (tid == 0) phiPrev[0] = 1.f;
    *reinterpret_cast<float4*>(p + j0) =
        make_float4(phiPrev[0], phiPrev[1], phiPrev[2], phiPrev[3]);
    *reinterpret_cast<float4*>(p + j0 + 4) =
        make_float4(phiPrev[4], phiPrev[5], phiPrev[6], phiPrev[7]);

    float curLeft;
    {
        const float* r = p + 1024;
        float4 c0 = *reinterpret_cast<const float4*>(r + j0);
        float4 c1 = *reinterpret_cast<const float4*>(r + j0 + 4);
        cur[0] = c0.x; cur[1] = c0.y; cur[2] = c0.z; cur[3] = c0.w;
        cur[4] = c1.x; cur[5] = c1.y; cur[6] = c1.z; cur[7] = c1.w;
        curLeft = (tid == 0) ? 0.f : r[j0 - 1];
    }

    for (int i = 1; i < 1024; i++) {
        float nxt[8];
        float nxtLeft = 0.f;
        if (i + 1 < 1024) {
            const float* r = p + (size_t)(i + 1) * 1024;
            float4 c0 = *reinterpret_cast<const float4*>(r + j0);
            float4 c1 = *reinterpret_cast<const float4*>(r + j0 + 4);
            nxt[0] = c0.x; nxt[1] = c0.y; nxt[2] = c0.z; nxt[3] = c0.w;
            nxt[4] = c1.x; nxt[5] = c1.y; nxt[6] = c1.z; nxt[7] = c1.w;
            nxtLeft = (tid == 0) ? 0.f : r[j0 - 1];
        }

        float A[8], a[8];
        A[0] = (tid == 0) ? 0.f : (1.f - curLeft);
#pragma unroll
        for (int x = 1; x < 8; x++) A[x] = 1.f - cur[x - 1];
#pragma unroll
        for (int x = 0; x < 8; x++) a[x] = phiPrev[x] * pPrev[x];

        float Ac = A[0], bc = a[0];
#pragma unroll
        for (int x = 1; x < 8; x++) {
            bc = fmaf(bc, A[x], a[x]);
            Ac *= A[x];
        }

        float sA = Ac, sB = bc;
#pragma unroll
        for (int d = 1; d < 32; d <<= 1) {
            float oA = __shfl_up_sync(0xffffffffu, sA, d);
            float oB = __shfl_up_sync(0xffffffffu, sB, d);
            if (lane >= d) {
                sB = fmaf(oB, sA, sB);
                sA = oA * sA;
            }
        }

        const int par = i & 1;
        if (lane == 31) {
            aggA[par][wid] = sA;
            aggB[par][wid] = sB;
        }
        __syncthreads();

        float yw = 0.f;
#pragma unroll
        for (int w = 0; w < 3; w++)
            if (w < wid) yw = fmaf(yw, aggA[par][w], aggB[par][w]);

        float eA = __shfl_up_sync(0xffffffffu, sA, 1);
        float eB = __shfl_up_sync(0xffffffffu, sB, 1);
        if (lane == 0) { eA = 1.f; eB = 0.f; }
        float y = fmaf(yw, eA, eB);

#pragma unroll
        for (int x = 0; x < 8; x++) {
            y = fmaf(A[x], y, a[x]);
            phiPrev[x] = y;
        }

        float* orow = p + (size_t)i * 1024 + j0;
        *reinterpret_cast<float4*>(orow) =
            make_float4(phiPrev[0], phiPrev[1], phiPrev[2], phiPrev[3]);
        *reinterpret_cast<float4*>(orow + 4) =
            make_float4(phiPrev[4], phiPrev[5], phiPrev[6], phiPrev[7]);

#pragma unroll
        for (int x = 0; x < 8; x++) pPrev[x] = cur[x];
        if (i + 1 < 1024) {
#pragma unroll
            for (int x = 0; x < 8; x++) cur[x] = nxt[x];
            curLeft = nxtLeft;
        }
    }
}

// ---------------- launch ----------------
extern "C" void kernel_launch(void* const* d_in, const int* in_sizes, int n_in,
                              void* d_out, int out_size) {
    (void)in_sizes; (void)n_in; (void)out_size;
    const float* query = (const float*)d_in[0];
    const float* key   = (const float*)d_in[1];
    const float* value = (const float*)d_in[2];
    const float* Win   = (const float*)d_in[3];
    const float* bin   = (const float*)d_in[4];
    const float* Wout  = (const float*)d_in[5];
    const float* bout  = (const float*)d_in[6];
    float* out = (float*)d_out;

    float *Q, *Kb, *Vb, *VT, *P, *XO;
    cudaGetSymbolAddress((void**)&Q, g_Q);
    cudaGetSymbolAddress((void**)&Kb, g_K);
    cudaGetSymbolAddress((void**)&Vb, g_V);
    cudaGetSymbolAddress((void**)&VT, g_VT);
    cudaGetSymbolAddress((void**)&P, g_P);
    cudaGetSymbolAddress((void**)&XO, g_XO);

    constexpr int SM128 = 2 * 128 * 128 + 2 * 128 * 128;  // 65536
    constexpr int SM64  = 2 * 128 * 128 + 2 * 64 * 128;   // 49152
    cudaFuncSetAttribute((const void*)gemm_tc<128, 2, 4, 0, 1>,
                         cudaFuncAttributeMaxDynamicSharedMemorySize, SM128);
    cudaFuncSetAttribute((const void*)gemm_tc<128, 2, 4, 3, 1>,
                         cudaFuncAttributeMaxDynamicSharedMemorySize, SM128);
    cudaFuncSetAttribute((const void*)gemm_tc<128, 2, 4, 1, 2>,
                         cudaFuncAttributeMaxDynamicSharedMemorySize, SM128);
    cudaFuncSetAttribute((const void*)gemm_tc<64, 4, 2, 2, 0>,
                         cudaFuncAttributeMaxDynamicSharedMemorySize, SM64);

    // Q projection: Q(2048x1024) = query @ Wq^T ; B operand = Win rows 0..1023 (N,K) direct
    gemm_tc<128, 2, 4, 0, 1><<<dim3(8, 16, 1), 256, SM128>>>(
        query, Win, Q, bin, nullptr, nullptr, 1024, 1024, 1024, 1024);

    // K & V projections fused (z=0: key->Kb, z=1: value->Vb); B = Win rows 1024..1535
    gemm_tc<128, 2, 4, 3, 1><<<dim3(2, 16, 2), 256, SM128>>>(
        key, Win, Kb, bin, value, Vb, 1024, 1024, 1024, 256);

    // V transpose -> (embed x token) for phi@V B operand
    {
        dim3 tb(32, 8);
        transpose_kernel<<<dim3(256 / 32, 2048 / 32), tb>>>(Vb, VT, 2048, 256);
    }

    // scores per head: P = clamp(sigmoid(Qh @ Kh^T), eps, 1-eps); B operand = Kproj directly
    gemm_tc<128, 2, 4, 1, 2><<<dim3(8, 8, 32), 256, SM128>>>(
        Q, Kb, P, nullptr, nullptr, nullptr, 64, 1024, 256, 1024);

    // monotonic attention recurrence (in place: P -> phi)
    monotonic_scan_kernel<<<32, 128>>>(P);

    // O = phi @ V per head (B operand = VT slice), scattered into XO head columns
    gemm_tc<64, 4, 2, 2, 0><<<dim3(1, 8, 32), 256, SM64>>>(
        P, VT, XO, nullptr, nullptr, nullptr, 1024, 1024, 2048, 1024);

    // output projection: out = XO @ Wout^T + bout ; B operand = Wout (N,K) direct
    gemm_tc<128, 2, 4, 0, 1><<<dim3(8, 16, 1), 256, SM128>>>(
        XO, Wout, out, bout, nullptr, nullptr, 1024, 1024, 1024, 1024);
}

// round 17
// speedup vs baseline: 1.6036x; 1.0739x over previous
#include <cuda_runtime.h>
#include <cuda_bf16.h>
#include <cstdint>

#define EPS_P 0.001f

// ---------------- scratch (device globals: no allocation, graph-safe) ----------------
__device__ float g_P[32 * 1024 * 1024];           // sigmoid probs (fp32, scan input)
__device__ float g_Vb[2048 * 256];                // projected V fp32 (transpose input)
__device__ __nv_bfloat16 g_qh[2048 * 1024], g_ql[2048 * 1024];   // query cvt
__device__ __nv_bfloat16 g_kh[2048 * 1024], g_kl[2048 * 1024];   // key cvt
__device__ __nv_bfloat16 g_vh[2048 * 1024], g_vl[2048 * 1024];   // value cvt
__device__ __nv_bfloat16 g_WinH[1536 * 1024], g_WinL[1536 * 1024];
__device__ __nv_bfloat16 g_WoutH[1024 * 1024], g_WoutL[1024 * 1024];
__device__ __nv_bfloat16 g_Qh[2048 * 1024], g_Ql[2048 * 1024];   // projected Q
__device__ __nv_bfloat16 g_Kh[2048 * 256], g_Kl[2048 * 256];     // projected K
__device__ __nv_bfloat16 g_VTh[256 * 2048], g_VTl[256 * 2048];   // V transposed
__device__ __nv_bfloat16 g_PhiH[32 * 1024 * 1024], g_PhiL[32 * 1024 * 1024]; // phi
__device__ __nv_bfloat16 g_XOh[2048 * 1024], g_XOl[2048 * 1024]; // attn out

// ---------------- helpers ----------------
__device__ __forceinline__ uint32_t smem_u32(const void* p) {
    uint32_t a;
    asm("{ .reg .u64 t; cvta.to.shared.u64 t, %1; cvt.u32.u64 %0, t; }" : "=r"(a) : "l"(p));
    return a;
}
__device__ __forceinline__ uint32_t sw128(uint32_t off) { return off ^ ((off >> 3) & 0x70); }

__device__ __forceinline__ void ldsm_x4(uint32_t (&r)[4], uint32_t addr) {
    asm volatile("ldmatrix.sync.aligned.m8n8.x4.shared.b16 {%0,%1,%2,%3}, [%4];"
                 : "=r"(r[0]), "=r"(r[1]), "=r"(r[2]), "=r"(r[3]) : "r"(addr));
}
__device__ __forceinline__ void ldsm_x2(uint32_t (&r)[2], uint32_t addr) {
    asm volatile("ldmatrix.sync.aligned.m8n8.x2.shared.b16 {%0,%1}, [%2];"
                 : "=r"(r[0]), "=r"(r[1]) : "r"(addr));
}
__device__ __forceinline__ void mma16816(float (&c)[4], const uint32_t (&a)[4],
                                         const uint32_t (&b)[2]) {
    asm volatile(
        "mma.sync.aligned.m16n8k16.row.col.f32.bf16.bf16.f32 "
        "{%0,%1,%2,%3}, {%4,%5,%6,%7}, {%8,%9}, {%0,%1,%2,%3};"
        : "+f"(c[0]), "+f"(c[1]), "+f"(c[2]), "+f"(c[3])
        : "r"(a[0]), "r"(a[1]), "r"(a[2]), "r"(a[3]), "r"(b[0]), "r"(b[1]));
}

// write a float pair as (hi bf162, lo bf162) to separate planes
__device__ __forceinline__ void wr_hl2(__nv_bfloat16* H, __nv_bfloat16* L, float a, float b) {
    __nv_bfloat16 ha = __float2bfloat16_rn(a);
    __nv_bfloat16 hb = __float2bfloat16_rn(b);
    __nv_bfloat162 Hp; Hp.x = ha; Hp.y = hb;
    __nv_bfloat162 Lp = __floats2bfloat162_rn(a - __bfloat162float(ha), b - __bfloat162float(hb));
    *reinterpret_cast<__nv_bfloat162*>(H) = Hp;
    *reinterpret_cast<__nv_bfloat162*>(L) = Lp;
}

// ---------------- elementwise fp32 -> bf16 hi/lo conversion ----------------
__global__ void cvt_hl_kernel(const float* __restrict__ src, __nv_bfloat16* __restrict__ h,
                              __nv_bfloat16* __restrict__ l, int n4) {
    int i = blockIdx.x * blockDim.x + threadIdx.x;
    if (i < n4) {
        float4 v = reinterpret_cast<const float4*>(src)[i];
        wr_hl2(h + 4 * i, l + 4 * i, v.x, v.y);
        wr_hl2(h + 4 * i + 2, l + 4 * i + 2, v.z, v.w);
    }
}

// ---------------- warp-MMA split-precision GEMM (bf16 hi/lo operands) ----------------
// C(m,n) = sum_k A[m,k]*B[n,k];  D = AhBh + AhBl + AlBh (fp32 accum; lo*lo dropped).
// Double-buffered smem (2 stages), one barrier per 64-wide K chunk; STS of chunk c+1 and
// LDG of chunk c+2 overlap the MMA of chunk c (no ALU cvt in the mainloop at all).
// MODE 0: plain. 1: scores. 2: phi@V. 3: fused K/V projection (z&1 selects operand/output).
// EPI 0: none,h/l out. 1: +bias,fp32 out. 2: sigmoid-clamp,fp32 out. 3: +bias,h/l out.
// EPI 4: +bias, z&1 ? fp32 : h/l (KV proj: K->h/l, V->fp32).
template <int BN, int WARPS_M, int WARPS_N, int MODE, int EPI>
__global__ void __launch_bounds__(256)
gemm_tc(const __nv_bfloat16* __restrict__ Ah, const __nv_bfloat16* __restrict__ Al,
        const __nv_bfloat16* __restrict__ A2h, const __nv_bfloat16* __restrict__ A2l,
        const __nv_bfloat16* __restrict__ Bh, const __nv_bfloat16* __restrict__ Bl,
        float* __restrict__ Cf, __nv_bfloat16* __restrict__ Ch, __nv_bfloat16* __restrict__ Cl,
        const float* __restrict__ bias, int K, int lda, int ldb, int ldc) {
    constexpr int NT = 256;
    static_assert(WARPS_M * WARPS_N == 8, "8 warps");
    constexpr int WM = 128 / WARPS_M;
    constexpr int WN = BN / WARPS_N;
    constexpr int MSUB = WM / 16;
    constexpr int NSUB = WN / 8;
    constexpr int CPTA = 128 * 8 / NT;   // 16B chunks/thread per A plane
    constexpr int CPTB = BN * 8 / NT;
    constexpr int ABYTES = 128 * 128;    // one bf16 tile: 128 rows x 128B
    constexpr int BBYTES = BN * 128;
    constexpr int STAGE = 2 * ABYTES + 2 * BBYTES;  // Ah|Al|Bh|Bl
    extern __shared__ char smem[];

    const int tid = threadIdx.x;
    const int wid = tid >> 5;
    const int lane = tid & 31;
    const int warp_m = wid % WARPS_M;
    const int warp_n = wid / WARPS_M;
    const uint32_t sb = smem_u32(smem);

    const int z = blockIdx.z;
    if constexpr (MODE == 1) {
        size_t ao = (size_t)(z >> 4) * 1048576 + (z & 15) * 64;
        size_t bo = (size_t)(z >> 4) * 262144 + (z & 3) * 64;
        Ah += ao; Al += ao; Bh += bo; Bl += bo;
        Cf += (size_t)z << 20;
    } else if constexpr (MODE == 2) {
        size_t ao = (size_t)z << 20;
        size_t bo = (size_t)(z & 3) * 131072 + (z >> 4) * 1024;
        size_t co = (size_t)(z >> 4) * 1048576 + (z & 15) * 64;
        Ah += ao; Al += ao; Bh += bo; Bl += bo; Ch += co; Cl += co;
    } else if constexpr (MODE == 3) {
        if (z & 1) { Ah = A2h; Al = A2l; }
        size_t bo = (size_t)(z & 1) * 262144;
        Bh += bo; Bl += bo;
        bias += (z & 1) * 256;
    }

    const int mBlk = blockIdx.y * 128;
    const int nBlk = blockIdx.x * BN;
    const int nK = K >> 6;

    float acc[MSUB][NSUB][4];
#pragma unroll
    for (int ms = 0; ms < MSUB; ms++)
#pragma unroll
        for (int ns = 0; ns < NSUB; ns++)
#pragma unroll
            for (int i = 0; i < 4; i++) acc[ms][ns][i] = 0.f;

    uint4 aH[CPTA], aL[CPTA], bH[CPTB], bL[CPTB];
    auto loadAB = [&](int kt) {
#pragma unroll
        for (int q = 0; q < CPTA; q++) {
            int v = tid + q * NT;
            int r = v >> 3, g = v & 7;
            size_t off = (size_t)(mBlk + r) * lda + kt * 64 + g * 8;
            aH[q] = *reinterpret_cast<const uint4*>(Ah + off);
            aL[q] = *reinterpret_cast<const uint4*>(Al + off);
        }
#pragma unroll
        for (int q = 0; q < CPTB; q++) {
            int v = tid + q * NT;
            int n = v >> 3, g = v & 7;
            size_t off = (size_t)(nBlk + n) * ldb + kt * 64 + g * 8;
            bH[q] = *reinterpret_cast<const uint4*>(Bh + off);
            bL[q] = *reinterpret_cast<const uint4*>(Bl + off);
        }
    };
    auto stsAB = [&](int s) {
        char* st = smem + s * STAGE;
#pragma unroll
        for (int q = 0; q < CPTA; q++) {
            int v = tid + q * NT;
            int r = v >> 3, g = v & 7;
            uint32_t off = sw128((uint32_t)(r * 128 + g * 16));
            *reinterpret_cast<uint4*>(st + off) = aH[q];
            *reinterpret_cast<uint4*>(st + ABYTES + off) = aL[q];
        }
#pragma unroll
        for (int q = 0; q < CPTB; q++) {
            int v = tid + q * NT;
            int n = v >> 3, g = v & 7;
            uint32_t off = sw128((uint32_t)(n * 128 + g * 16));
            *reinterpret_cast<uint4*>(st + 2 * ABYTES + off) = bH[q];
            *reinterpret_cast<uint4*>(st + 2 * ABYTES + BBYTES + off) = bL[q];
        }
    };

    // ldmatrix address bases (byte offsets within a tile)
    uint32_t aRow[MSUB], bRow[NSUB];
#pragma unroll
    for (int ms = 0; ms < MSUB; ms++)
        aRow[ms] = (uint32_t)((warp_m * WM + ms * 16 + (lane & 15)) * 128 + (lane & 16));
#pragma unroll
    for (int ns = 0; ns < NSUB; ns++)
        bRow[ns] = (uint32_t)((warp_n * WN + ns * 8 + (lane & 7)) * 128 +
                              (((lane >> 3) & 1) << 4));

    // prologue
    loadAB(0);
    stsAB(0);
    if (nK > 1) loadAB(1);
    __syncthreads();

    for (int c = 0; c < nK; c++) {
        const int cur = c & 1;
        if (c + 1 < nK) stsAB(cur ^ 1);          // regs hold chunk c+1
        if (c + 2 < nK) loadAB(c + 2);           // refill regs with chunk c+2
        const uint32_t base = sb + cur * STAGE;
#pragma unroll
        for (int ks = 0; ks < 4; ks++) {
            uint32_t afh[MSUB][4], afl[MSUB][4], bfh[NSUB][2], bfl[NSUB][2];
#pragma unroll
            for (int ms = 0; ms < MSUB; ms++) {
                uint32_t off = sw128(aRow[ms] + ks * 32);
                ldsm_x4(afh[ms], base + off);
                ldsm_x4(afl[ms], base + ABYTES + off);
            }
#pragma unroll
            for (int ns = 0; ns < NSUB; ns++) {
                uint32_t off = sw128(bRow[ns] + ks * 32);
                ldsm_x2(bfh[ns], base + 2 * ABYTES + off);
                ldsm_x2(bfl[ns], base + 2 * ABYTES + BBYTES + off);
            }
#pragma unroll
            for (int ms = 0; ms < MSUB; ms++)
#pragma unroll
                for (int ns = 0; ns < NSUB; ns++) {
                    mma16816(acc[ms][ns], afh[ms], bfh[ns]);
                    mma16816(acc[ms][ns], afh[ms], bfl[ns]);
                    mma16816(acc[ms][ns], afl[ms], bfh[ns]);
                }
        }
        __syncthreads();
    }

    // epilogue: c0=(g,2q) c1=(g,2q+1) c2=(g+8,2q) c3=(g+8,2q+1)
    const int g = lane >> 2;
    const int qq = lane & 3;
#pragma unroll
    for (int ms = 0; ms < MSUB; ms++) {
#pragma unroll
        for (int ns = 0; ns < NSUB; ns++) {
            int r0 = mBlk + warp_m * WM + ms * 16 + g;
            int c0 = nBlk + warp_n * WN + ns * 8 + qq * 2;
            float v[4] = {acc[ms][ns][0], acc[ms][ns][1], acc[ms][ns][2], acc[ms][ns][3]};
            if constexpr (EPI == 1 || EPI == 3 || EPI == 4) {
                float b0 = __ldg(&bias[c0]);
                float b1 = __ldg(&bias[c0 + 1]);
                v[0] += b0; v[1] += b1; v[2] += b0; v[3] += b1;
            } else if constexpr (EPI == 2) {
#pragma unroll
                for (int i = 0; i < 4; i++) {
                    float s = 1.f / (1.f + __expf(-v[i]));
                    v[i] = fminf(fmaxf(s, EPS_P), 1.f - EPS_P);
                }
            }
            size_t i0 = (size_t)r0 * ldc + c0;
            size_t i1 = (size_t)(r0 + 8) * ldc + c0;
            bool f32out = (EPI == 1 || EPI == 2) || (EPI == 4 && (z & 1));
            if (f32out) {
                *reinterpret_cast<float2*>(Cf + i0) = make_float2(v[0], v[1]);
                *reinterpret_cast<float2*>(Cf + i1) = make_float2(v[2], v[3]);
            } else {
                wr_hl2(Ch + i0, Cl + i0, v[0], v[1]);
                wr_hl2(Ch + i1, Cl + i1, v[2], v[3]);
            }
        }
    }
}

// ---------------- transpose fp32 -> bf16 hi/lo planes: out(C x R) = in(R x C)^T --------
__global__ void transpose_hl_kernel(const float* __restrict__ in, __nv_bfloat16* __restrict__ oh,
                                    __nv_bfloat16* __restrict__ ol, int R, int C) {
    __shared__ float tile[32][33];
    int c0 = blockIdx.x * 32;
    int r0 = blockIdx.y * 32;
    int x = threadIdx.x, y0 = threadIdx.y;
#pragma unroll
    for (int yy = y0; yy < 32; yy += 8) {
        int r = r0 + yy, c = c0 + x;
        if (r < R && c < C) tile[yy][x] = in[(size_t)r * C + c];
    }
    __syncthreads();
#pragma unroll
    for (int yy = y0; yy < 32; yy += 8) {
        int c = c0 + yy, r = r0 + x;
        if (r < R && c < C) {
            float v = tile[x][yy];
            __nv_bfloat16 h = __float2bfloat16_rn(v);
            oh[(size_t)c * R + r] = h;
            ol[(size_t)c * R + r] = __float2bfloat16_rn(v - __bfloat162float(h));
        }
    }
}

// ---------------- monotonic attention scan: P (fp32) -> phi (bf16 hi/lo planes) --------
// phi[i,j] = (1 - p[i,j-1]) * phi[i,j-1] + p[i-1,j] * phi[i-1,j]; phi[0] = onehot(0).
__global__ void __launch_bounds__(128) monotonic_scan_kernel(
    const float* __restrict__ P, __nv_bfloat16* __restrict__ PhiH,
    __nv_bfloat16* __restrict__ PhiL) {
    const float* p = P + ((size_t)blockIdx.x << 20);
    __nv_bfloat16* ph = PhiH + ((size_t)blockIdx.x << 20);
    __nv_bfloat16* pl = PhiL + ((size_t)blockIdx.x << 20);
    const int tid = threadIdx.x;
    const int lane = tid & 31;
    const int wid = tid >> 5;
    const int j0 = tid << 3;
    __shared__ float aggA[2][4], aggB[2][4];

    auto store8 = [&](size_t base, const float (&v)[8]) {
        uint32_t hp[4], lp[4];
#pragma unroll
        for (int x = 0; x < 4; x++) {
            __nv_bfloat16 h0 = __float2bfloat16_rn(v[2 * x]);
            __nv_bfloat16 h1 = __float2bfloat16_rn(v[2 * x + 1]);
            __nv_bfloat162 Hp; Hp.x = h0; Hp.y = h1;
            __nv_bfloat162 Lp = __floats2bfloat162_rn(v[2 * x] - __bfloat162float(h0),
                                                      v[2 * x + 1] - __bfloat162float(h1));
            hp[x] = *reinterpret_cast<uint32_t*>(&Hp);
            lp[x] = *reinterpret_cast<uint32_t*>(&Lp);
        }
        *reinterpret_cast<uint4*>(ph + base + j0) = make_uint4(hp[0], hp[1], hp[2], hp[3]);
        *reinterpret_cast<uint4*>(pl + base + j0) = make_uint4(lp[0], lp[1], lp[2], lp[3]);
    };

    float pPrev[8], phiPrev[8], cur[8];
    {
        float4 t0 = *reinterpret_cast<const float4*>(p + j0);
        float4 t1 = *reinterpret_cast<const float4*>(p + j0 + 4);
        pPrev[0] = t0.x; pPrev[1] = t0.y; pPrev[2] = t0.z; pPrev[3] = t0.w;
        pPrev[4] = t1.x; pPrev[5] = t1.y; pPrev[6] = t1.z; pPrev[7] = t1.w;
    }
#pragma unroll
    for (int x = 0; x < 8; x++) phiPrev[x] = 0.f;
    if (tid == 0) phiPrev[0] = 1.f;
    store8(0, phiPrev);

    float curLeft;
    {
        const float* r = p + 1024;
        float4 c0 = *reinterpret_cast<const float4*>(r + j0);
        float4 c1 = *reinterpret_cast<const float4*>(r + j0 + 4);
        cur[0] = c0.x; cur[1] = c0.y; cur[2] = c0.z; cur[3] = c0.w;
        cur[4] = c1.x; cur[5] = c1.y; cur[6] = c1.z; cur[7] = c1.w;
        curLeft = (tid == 0) ? 0.f : r[j0 - 1];
    }

    for (int i = 1; i < 1024; i++) {
        float nxt[8];
        float nxtLeft = 0.f;
        if (i + 1 < 1024) {
            const float* r = p + (size_t)(i + 1) * 1024;
            float4 c0 = *reinterpret_cast<const float4*>(r + j0);
            float4 c1 = *reinterpret_cast<const float4*>(r + j0 + 4);
            nxt[0] = c0.x; nxt[1] = c0.y; nxt[2] = c0.z; nxt[3] = c0.w;
            nxt[4] = c1.x; nxt[5] = c1.y; nxt[6] = c1.z; nxt[7] = c1.w;
            nxtLeft = (tid == 0) ? 0.f : r[j0 - 1];
        }

        float A[8], a[8];
        A[0] = (tid == 0) ? 0.f : (1.f - curLeft);
#pragma unroll
        for (int x = 1; x < 8; x++) A[x] = 1.f - cur[x - 1];
#pragma unroll
        for (int x = 0; x < 8; x++) a[x] = phiPrev[x] * pPrev[x];

        float Ac = A[0], bc = a[0];
#pragma unroll
        for (int x = 1; x < 8; x++) {
            bc = fmaf(bc, A[x], a[x]);
            Ac *= A[x];
        }

        float sA = Ac, sB = bc;
#pragma unroll
        for (int d = 1; d < 32; d <<= 1) {
            float oA = __shfl_up_sync(0xffffffffu, sA, d);
            float oB = __shfl_up_sync(0xffffffffu, sB, d);
            if (lane >= d) {
                sB = fmaf(oB, sA, sB);
                sA = oA * sA;
            }
        }

        const int par = i & 1;
        if (lane == 31) {
            aggA[par][wid] = sA;
            aggB[par][wid] = sB;
        }
        __syncthreads();

        float yw = 0.f;
#pragma unroll
        for (int w = 0; w < 3; w++)
            if (w < wid) yw = fmaf(yw, aggA[par][w], aggB[par][w]);

        float eA = __shfl_up_sync(0xffffffffu, sA, 1);
        float eB = __shfl_up_sync(0xffffffffu, sB, 1);
        if (lane == 0) { eA = 1.f; eB = 0.f; }
        float y = fmaf(yw, eA, eB);

#pragma unroll
        for (int x = 0; x < 8; x++) {
            y = fmaf(A[x], y, a[x]);
            phiPrev[x] = y;
        }

        store8((size_t)i * 1024, phiPrev);

#pragma unroll
        for (int x = 0; x < 8; x++) pPrev[x] = cur[x];
        if (i + 1 < 1024) {
#pragma unroll
            for (int x = 0; x < 8; x++) cur[x] = nxt[x];
            curLeft = nxtLeft;
        }
    }
}

// ---------------- launch ----------------
extern "C" void kernel_launch(void* const* d_in, const int* in_sizes, int n_in,
                              void* d_out, int out_size) {
    (void)in_sizes; (void)n_in; (void)out_size;
    const float* query = (const float*)d_in[0];
    const float* key   = (const float*)d_in[1];
    const float* value = (const float*)d_in[2];
    const float* Win   = (const float*)d_in[3];
    const float* bin   = (const float*)d_in[4];
    const float* Wout  = (const float*)d_in[5];
    const float* bout  = (const float*)d_in[6];
    float* out = (float*)d_out;

    float *P, *Vb;
    __nv_bfloat16 *qh, *ql, *kh, *kl, *vh, *vl, *WinH, *WinL, *WoutH, *WoutL;
    __nv_bfloat16 *Qh, *Ql, *Kh, *Kl, *VTh, *VTl, *PhiH, *PhiL, *XOh, *XOl;
    cudaGetSymbolAddress((void**)&P, g_P);
    cudaGetSymbolAddress((void**)&Vb, g_Vb);
    cudaGetSymbolAddress((void**)&qh, g_qh);  cudaGetSymbolAddress((void**)&ql, g_ql);
    cudaGetSymbolAddress((void**)&kh, g_kh);  cudaGetSymbolAddress((void**)&kl, g_kl);
    cudaGetSymbolAddress((void**)&vh, g_vh);  cudaGetSymbolAddress((void**)&vl, g_vl);
    cudaGetSymbolAddress((void**)&WinH, g_WinH);  cudaGetSymbolAddress((void**)&WinL, g_WinL);
    cudaGetSymbolAddress((void**)&WoutH, g_WoutH); cudaGetSymbolAddress((void**)&WoutL, g_WoutL);
    cudaGetSymbolAddress((void**)&Qh, g_Qh);  cudaGetSymbolAddress((void**)&Ql, g_Ql);
    cudaGetSymbolAddress((void**)&Kh, g_Kh);  cudaGetSymbolAddress((void**)&Kl, g_Kl);
    cudaGetSymbolAddress((void**)&VTh, g_VTh); cudaGetSymbolAddress((void**)&VTl, g_VTl);
    cudaGetSymbolAddress((void**)&PhiH, g_PhiH); cudaGetSymbolAddress((void**)&PhiL, g_PhiL);
    cudaGetSymbolAddress((void**)&XOh, g_XOh); cudaGetSymbolAddress((void**)&XOl, g_XOl);

    constexpr int SM128 = 2 * (2 * 16384 + 2 * 128 * 128);  // 131072
    constexpr int SM64  = 2 * (2 * 16384 + 2 * 64 * 128);   // 98304
    cudaFuncSetAttribute((const void*)gemm_tc<128, 2, 4, 0, 3>,
                         cudaFuncAttributeMaxDynamicSharedMemorySize, SM128);
    cudaFuncSetAttribute((const void*)gemm_tc<128, 2, 4, 3, 4>,
                         cudaFuncAttributeMaxDynamicSharedMemorySize, SM128);
    cudaFuncSetAttribute((const void*)gemm_tc<128, 2, 4, 1, 2>,
                         cudaFuncAttributeMaxDynamicSharedMemorySize, SM128);
    cudaFuncSetAttribute((const void*)gemm_tc<64, 4, 2, 2, 0>,
                         cudaFuncAttributeMaxDynamicSharedMemorySize, SM64);
    cudaFuncSetAttribute((const void*)gemm_tc<128, 2, 4, 0, 1>,
                         cudaFuncAttributeMaxDynamicSharedMemorySize, SM128);

    // --- input conversions to bf16 hi/lo planes ---
    cvt_hl_kernel<<<2048, 256>>>(query, qh, ql, 2048 * 1024 / 4);
    cvt_hl_kernel<<<2048, 256>>>(key, kh, kl, 2048 * 1024 / 4);
    cvt_hl_kernel<<<2048, 256>>>(value, vh, vl, 2048 * 1024 / 4);
    cvt_hl_kernel<<<1536, 256>>>(Win, WinH, WinL, 1536 * 1024 / 4);
    cvt_hl_kernel<<<1024, 256>>>(Wout, WoutH, WoutL, 1024 * 1024 / 4);

    // Q projection: Q = query @ Wq^T + bq -> h/l planes
    gemm_tc<128, 2, 4, 0, 3><<<dim3(8, 16, 1), 256, SM128>>>(
        qh, ql, nullptr, nullptr, WinH, WinL, nullptr, Qh, Ql, bin, 1024, 1024, 1024, 1024);

    // K & V projections fused (z&1==0: key -> Kh/Kl; z&1==1: value -> Vb fp32)
    gemm_tc<128, 2, 4, 3, 4><<<dim3(2, 16, 2), 256, SM128>>>(
        kh, kl, vh, vl, WinH + 1024 * 1024, WinL + 1024 * 1024,
        Vb, Kh, Kl, bin + 1024, 1024, 1024, 1024, 256);

    // V transpose -> (embed x token) h/l planes
    {
        dim3 tb(32, 8);
        transpose_hl_kernel<<<dim3(256 / 32, 2048 / 32), tb>>>(Vb, VTh, VTl, 2048, 256);
    }

    // scores per head: P = clamp(sigmoid(Qh @ Kh^T), eps, 1-eps) fp32
    gemm_tc<128, 2, 4, 1, 2><<<dim3(8, 8, 32), 256, SM128>>>(
        Qh, Ql, nullptr, nullptr, Kh, Kl, P, nullptr, nullptr, nullptr, 64, 1024, 256, 1024);

    // monotonic attention recurrence: P -> phi h/l planes
    monotonic_scan_kernel<<<32, 128>>>(P, PhiH, PhiL);

    // O = phi @ V per head -> XO h/l planes (token-major, per-head cols)
    gemm_tc<64, 4, 2, 2, 0><<<dim3(1, 8, 32), 256, SM64>>>(
        PhiH, PhiL, nullptr, nullptr, VTh, VTl, nullptr, XOh, XOl, nullptr,
        1024, 1024, 2048, 1024);

    // output projection: out = XO @ Wout^T + bout (fp32)
    gemm_tc<128, 2, 4, 0, 1><<<dim3(8, 16, 1), 256, SM128>>>(
        XOh, XOl, nullptr, nullptr, WoutH, WoutL, out, nullptr, nullptr, bout,
        1024, 1024, 1024, 1024);
}